// round 1
// baseline (speedup 1.0000x reference)
#include <cuda_runtime.h>
#include <cuda_bf16.h>

// Node2GraphAttention:
//   coef[i] = sigmoid( dot(n_emb[i], g_emb[batch[i]]) )
//   out[g]  = sum_{i: batch[i]==g} coef[i] * n_emb[i]
// n_batch is SORTED -> warp-local register accumulation per segment,
// atomicAdd only at segment boundaries / warp-range edges.

#define D 128
#define D4 (D / 4)           // 32 float4 per row -> one float4 per lane
#define NODES_PER_WARP 128
#define THREADS 256
#define WARPS_PER_BLOCK (THREADS / 32)

__device__ int g_idx_is64;   // 1 if n_batch is int64, 0 if int32

// Detect index dtype: values are in [0, G) with G=10000 and the array is
// sorted ascending. Reinterpreted as int32:
//  - if data is int64 (LE), index N-1 (odd for even N) is a HIGH word == 0
//  - if data is int32, index N-1 is the max sorted value (>0 w.p. ~1)
__global__ void detect_idx_dtype_kernel(const int* __restrict__ nb32, int N) {
    if (threadIdx.x == 0 && blockIdx.x == 0) {
        g_idx_is64 = (nb32[N - 1] == 0) ? 1 : 0;
    }
}

__global__ void zero_out_kernel(float* __restrict__ out, int n) {
    int i = blockIdx.x * blockDim.x + threadIdx.x;
    if (i < n) out[i] = 0.0f;
}

__device__ __forceinline__ int load_batch(const void* __restrict__ nb, long i, int is64) {
    if (is64) return (int)(((const long long*)nb)[i]);
    return ((const int*)nb)[i];
}

__device__ __forceinline__ void flush_seg(float* __restrict__ out, int b, int lane,
                                          const float4& acc) {
    float* p = out + (long)b * D + lane * 4;
    atomicAdd(p + 0, acc.x);
    atomicAdd(p + 1, acc.y);
    atomicAdd(p + 2, acc.z);
    atomicAdd(p + 3, acc.w);
}

__global__ void __launch_bounds__(THREADS)
n2g_attention_kernel(const float4* __restrict__ n4,
                     const float4* __restrict__ g4,
                     const void*  __restrict__ nb,
                     float* __restrict__ out,
                     int N) {
    const int lane  = threadIdx.x & 31;
    const int wglob = (blockIdx.x * WARPS_PER_BLOCK) + (threadIdx.x >> 5);

    long start = (long)wglob * NODES_PER_WARP;
    if (start >= N) return;
    long end = start + NODES_PER_WARP;
    if (end > N) end = N;

    const int is64 = g_idx_is64;

    float4 acc = make_float4(0.f, 0.f, 0.f, 0.f);
    int cur_b = load_batch(nb, start, is64);

    #pragma unroll 2
    for (long i = start; i < end; ++i) {
        const int b = load_batch(nb, i, is64);
        const float4 nv = __ldg(&n4[i * D4 + lane]);
        const float4 gv = __ldg(&g4[(long)b * D4 + lane]);

        float d = nv.x * gv.x + nv.y * gv.y + nv.z * gv.z + nv.w * gv.w;
        #pragma unroll
        for (int o = 16; o > 0; o >>= 1)
            d += __shfl_xor_sync(0xffffffffu, d, o);

        const float coef = 1.0f / (1.0f + __expf(-d));

        if (b != cur_b) {
            flush_seg(out, cur_b, lane, acc);
            acc = make_float4(0.f, 0.f, 0.f, 0.f);
            cur_b = b;
        }

        acc.x += coef * nv.x;
        acc.y += coef * nv.y;
        acc.z += coef * nv.z;
        acc.w += coef * nv.w;
    }

    flush_seg(out, cur_b, lane, acc);
}

extern "C" void kernel_launch(void* const* d_in, const int* in_sizes, int n_in,
                              void* d_out, int out_size) {
    const float4* n4 = (const float4*)d_in[0];   // n_embedding [N,128] f32
    const float4* g4 = (const float4*)d_in[1];   // g_embedding [G,128] f32
    const void*   nb = d_in[2];                  // n_batch [N] int32 or int64
    float* out = (float*)d_out;                  // [G,128] f32

    const int N = in_sizes[0] / D;

    detect_idx_dtype_kernel<<<1, 32>>>((const int*)nb, N);

    zero_out_kernel<<<(out_size + 255) / 256, 256>>>(out, out_size);

    const int total_warps  = (N + NODES_PER_WARP - 1) / NODES_PER_WARP;
    const int total_blocks = (total_warps + WARPS_PER_BLOCK - 1) / WARPS_PER_BLOCK;
    n2g_attention_kernel<<<total_blocks, THREADS>>>(n4, g4, nb, out, N);
}

// round 2
// speedup vs baseline: 1.5108x; 1.5108x over previous
#include <cuda_runtime.h>
#include <cuda_bf16.h>

// Node2GraphAttention:
//   coef[i] = sigmoid( dot(n_emb[i], g_emb[batch[i]]) )
//   out[g]  = sum_{i: batch[i]==g} coef[i] * n_emb[i]
// n_batch is SORTED -> warp-local register accumulation per segment,
// atomicAdd only at segment boundaries / warp-range edges.

#define D 128
#define D4 (D / 4)           // 32 float4 per row -> one float4 per lane
#define NODES_PER_WARP 128
#define THREADS 256
#define WARPS_PER_BLOCK (THREADS / 32)

__device__ int g_idx_is64;   // 1 if n_batch is int64, 0 if int32

// Zero output AND detect index dtype (one launch -> 2 launches per call total,
// so ncu -s 5 -c 1 captures the MAIN kernel).
// Detection: values in [0,G) sorted ascending; reinterpreted as int32, element
// N-1 is a zero high word iff data is little-endian int64.
__global__ void init_kernel(float* __restrict__ out, int n,
                            const int* __restrict__ nb32, int N) {
    int i = blockIdx.x * blockDim.x + threadIdx.x;
    if (i < n) out[i] = 0.0f;
    if (i == 0) g_idx_is64 = (nb32[N - 1] == 0) ? 1 : 0;
}

__device__ __forceinline__ int load_batch(const void* __restrict__ nb, int i, int is64) {
    if (is64) return (int)(((const long long*)nb)[i]);
    return ((const int*)nb)[i];
}

__device__ __forceinline__ float sigmoidf_(float x) {
    return 1.0f / (1.0f + __expf(-x));
}

__device__ __forceinline__ float dot4(const float4& a, const float4& b) {
    return a.x * b.x + a.y * b.y + a.z * b.z + a.w * b.w;
}

__device__ __forceinline__ void flush_seg(float* __restrict__ out, int b, int lane,
                                          const float4& acc) {
    float* p = out + b * D + lane * 4;
    atomicAdd(p + 0, acc.x);
    atomicAdd(p + 1, acc.y);
    atomicAdd(p + 2, acc.z);
    atomicAdd(p + 3, acc.w);
}

__device__ __forceinline__ void acc_add(float4& acc, float c, const float4& nv) {
    acc.x += c * nv.x;
    acc.y += c * nv.y;
    acc.z += c * nv.z;
    acc.w += c * nv.w;
}

// Fused butterfly reduction of 4 per-lane partials -> 4 warp sums,
// sigmoid applied once (4 nodes in one MUFU instruction), then broadcast.
// 13 SHFL + 1 MUFU per 4 nodes (vs 20 SHFL + 4 MUFU naive).
__device__ __forceinline__ void reduce4_sigmoid(float d0, float d1, float d2, float d3,
                                                float& c0, float& c1, float& c2, float& c3,
                                                int lane) {
    const unsigned m = 0xffffffffu;
    float t0 = __shfl_xor_sync(m, d0, 16);
    float t1 = __shfl_xor_sync(m, d1, 16);
    float t2 = __shfl_xor_sync(m, d2, 16);
    float t3 = __shfl_xor_sync(m, d3, 16);
    bool hi16 = (lane & 16) != 0;
    float a = hi16 ? (d2 + t2) : (d0 + t0);
    float b = hi16 ? (d3 + t3) : (d1 + t1);
    float ta = __shfl_xor_sync(m, a, 8);
    float tb = __shfl_xor_sync(m, b, 8);
    bool hi8 = (lane & 8) != 0;
    float c = hi8 ? (b + tb) : (a + ta);
    c += __shfl_xor_sync(m, c, 4);
    c += __shfl_xor_sync(m, c, 2);
    c += __shfl_xor_sync(m, c, 1);
    // lane group (hi16,hi8) holds node (hi16*2 + hi8)'s full sum
    float s = sigmoidf_(c);
    c0 = __shfl_sync(m, s, 0);
    c1 = __shfl_sync(m, s, 8);
    c2 = __shfl_sync(m, s, 16);
    c3 = __shfl_sync(m, s, 24);
}

__global__ void __launch_bounds__(THREADS)
n2g_attention_kernel(const float4* __restrict__ n4,
                     const float4* __restrict__ g4,
                     const void*  __restrict__ nb,
                     float* __restrict__ out,
                     int N) {
    const int lane  = threadIdx.x & 31;
    const int wglob = (blockIdx.x * WARPS_PER_BLOCK) + (threadIdx.x >> 5);

    int start = wglob * NODES_PER_WARP;
    if (start >= N) return;
    int end = start + NODES_PER_WARP;
    if (end > N) end = N;

    const int is64 = g_idx_is64;

    float4 acc = make_float4(0.f, 0.f, 0.f, 0.f);
    int cur_b = load_batch(nb, start, is64);

    int i = start;
    for (; i + 4 <= end; i += 4) {
        // ---- front-batched independent loads (MLP 8) ----
        const int b0 = load_batch(nb, i + 0, is64);
        const int b1 = load_batch(nb, i + 1, is64);
        const int b2 = load_batch(nb, i + 2, is64);
        const int b3 = load_batch(nb, i + 3, is64);

        const float4 nv0 = __ldcs(&n4[(i + 0) * D4 + lane]);
        const float4 nv1 = __ldcs(&n4[(i + 1) * D4 + lane]);
        const float4 nv2 = __ldcs(&n4[(i + 2) * D4 + lane]);
        const float4 nv3 = __ldcs(&n4[(i + 3) * D4 + lane]);

        const float4 gv0 = __ldg(&g4[b0 * D4 + lane]);
        const float4 gv1 = __ldg(&g4[b1 * D4 + lane]);
        const float4 gv2 = __ldg(&g4[b2 * D4 + lane]);
        const float4 gv3 = __ldg(&g4[b3 * D4 + lane]);

        const float d0 = dot4(nv0, gv0);
        const float d1 = dot4(nv1, gv1);
        const float d2 = dot4(nv2, gv2);
        const float d3 = dot4(nv3, gv3);

        float c0, c1, c2, c3;
        reduce4_sigmoid(d0, d1, d2, d3, c0, c1, c2, c3, lane);

        // ---- ordered segment accumulation (rare flush branches) ----
        if (b0 != cur_b) { flush_seg(out, cur_b, lane, acc); acc = make_float4(0,0,0,0); cur_b = b0; }
        acc_add(acc, c0, nv0);
        if (b1 != cur_b) { flush_seg(out, cur_b, lane, acc); acc = make_float4(0,0,0,0); cur_b = b1; }
        acc_add(acc, c1, nv1);
        if (b2 != cur_b) { flush_seg(out, cur_b, lane, acc); acc = make_float4(0,0,0,0); cur_b = b2; }
        acc_add(acc, c2, nv2);
        if (b3 != cur_b) { flush_seg(out, cur_b, lane, acc); acc = make_float4(0,0,0,0); cur_b = b3; }
        acc_add(acc, c3, nv3);
    }

    // tail (only possible in the very last warp)
    for (; i < end; ++i) {
        const int b = load_batch(nb, i, is64);
        const float4 nv = __ldcs(&n4[i * D4 + lane]);
        const float4 gv = __ldg(&g4[b * D4 + lane]);
        float d = dot4(nv, gv);
        #pragma unroll
        for (int o = 16; o > 0; o >>= 1)
            d += __shfl_xor_sync(0xffffffffu, d, o);
        const float coef = sigmoidf_(d);
        if (b != cur_b) { flush_seg(out, cur_b, lane, acc); acc = make_float4(0,0,0,0); cur_b = b; }
        acc_add(acc, coef, nv);
    }

    flush_seg(out, cur_b, lane, acc);
}

extern "C" void kernel_launch(void* const* d_in, const int* in_sizes, int n_in,
                              void* d_out, int out_size) {
    const float4* n4 = (const float4*)d_in[0];   // n_embedding [N,128] f32
    const float4* g4 = (const float4*)d_in[1];   // g_embedding [G,128] f32
    const void*   nb = d_in[2];                  // n_batch [N] int32 or int64
    float* out = (float*)d_out;                  // [G,128] f32

    const int N = in_sizes[0] / D;

    init_kernel<<<(out_size + 255) / 256, 256>>>(out, out_size, (const int*)nb, N);

    const int total_warps  = (N + NODES_PER_WARP - 1) / NODES_PER_WARP;
    const int total_blocks = (total_warps + WARPS_PER_BLOCK - 1) / WARPS_PER_BLOCK;
    n2g_attention_kernel<<<total_blocks, THREADS>>>(n4, g4, nb, out, N);
}

// round 3
// speedup vs baseline: 1.7792x; 1.1776x over previous
#include <cuda_runtime.h>
#include <cuda_bf16.h>

// Node2GraphAttention:
//   coef[i] = sigmoid( dot(n_emb[i], g_emb[batch[i]]) )
//   out[g]  = sum_{i: batch[i]==g} coef[i] * n_emb[i]
// n_batch is SORTED -> warp-local register accumulation per segment,
// red.global.add.v4.f32 only at segment boundaries / warp-range edges.

#define D 128
#define D4 (D / 4)           // 32 float4 per row -> one float4 per lane
#define NODES_PER_WARP 32
#define THREADS 128
#define WARPS_PER_BLOCK (THREADS / 32)

__device__ int g_idx_is64;   // 1 if n_batch is int64, 0 if int32

// Zero output AND detect index dtype (2 launches per call total, so
// ncu -s 5 -c 1 captures the MAIN kernel).
// Detection: values in [0,G) sorted ascending; reinterpreted as int32,
// element N-1 is a zero high word iff data is little-endian int64.
__global__ void init_kernel(float* __restrict__ out, int n,
                            const int* __restrict__ nb32, int N) {
    int i = blockIdx.x * blockDim.x + threadIdx.x;
    if (i < n) out[i] = 0.0f;
    if (i == 0) g_idx_is64 = (nb32[N - 1] == 0) ? 1 : 0;
}

__device__ __forceinline__ int load_batch(const void* __restrict__ nb, int i, int is64) {
    if (is64) return (int)(((const long long*)nb)[i]);
    return ((const int*)nb)[i];
}

__device__ __forceinline__ float sigmoidf_(float x) {
    return 1.0f / (1.0f + __expf(-x));
}

__device__ __forceinline__ float dot4(const float4& a, const float4& b) {
    return a.x * b.x + a.y * b.y + a.z * b.z + a.w * b.w;
}

// One vector reduction instruction per lane (sm_90+), no return value.
__device__ __forceinline__ void flush_seg(float* __restrict__ out, int b, int lane,
                                          const float4& acc) {
    float* p = out + b * D + lane * 4;   // 16B aligned
    asm volatile("red.global.add.v4.f32 [%0], {%1, %2, %3, %4};"
                 :: "l"(p), "f"(acc.x), "f"(acc.y), "f"(acc.z), "f"(acc.w)
                 : "memory");
}

__device__ __forceinline__ void acc_add(float4& acc, float c, const float4& nv) {
    acc.x += c * nv.x;
    acc.y += c * nv.y;
    acc.z += c * nv.z;
    acc.w += c * nv.w;
}

// Fused butterfly reduction of 4 per-lane partials -> 4 warp sums,
// sigmoid applied once (4 nodes share one MUFU), then broadcast.
// 13 SHFL + 1 MUFU per 4 nodes (vs 20 SHFL + 4 MUFU naive).
__device__ __forceinline__ void reduce4_sigmoid(float d0, float d1, float d2, float d3,
                                                float& c0, float& c1, float& c2, float& c3,
                                                int lane) {
    const unsigned m = 0xffffffffu;
    float t0 = __shfl_xor_sync(m, d0, 16);
    float t1 = __shfl_xor_sync(m, d1, 16);
    float t2 = __shfl_xor_sync(m, d2, 16);
    float t3 = __shfl_xor_sync(m, d3, 16);
    bool hi16 = (lane & 16) != 0;
    float a = hi16 ? (d2 + t2) : (d0 + t0);
    float b = hi16 ? (d3 + t3) : (d1 + t1);
    float ta = __shfl_xor_sync(m, a, 8);
    float tb = __shfl_xor_sync(m, b, 8);
    bool hi8 = (lane & 8) != 0;
    float c = hi8 ? (b + tb) : (a + ta);
    c += __shfl_xor_sync(m, c, 4);
    c += __shfl_xor_sync(m, c, 2);
    c += __shfl_xor_sync(m, c, 1);
    float s = sigmoidf_(c);
    c0 = __shfl_sync(m, s, 0);
    c1 = __shfl_sync(m, s, 8);
    c2 = __shfl_sync(m, s, 16);
    c3 = __shfl_sync(m, s, 24);
}

__global__ void __launch_bounds__(THREADS)
n2g_attention_kernel(const float4* __restrict__ n4,
                     const float4* __restrict__ g4,
                     const void*  __restrict__ nb,
                     float* __restrict__ out,
                     int N) {
    const int lane  = threadIdx.x & 31;
    const int wglob = (blockIdx.x * WARPS_PER_BLOCK) + (threadIdx.x >> 5);

    int start = wglob * NODES_PER_WARP;
    if (start >= N) return;
    int end = start + NODES_PER_WARP;
    if (end > N) end = N;

    const int is64 = g_idx_is64;

    float4 acc = make_float4(0.f, 0.f, 0.f, 0.f);
    int cur_b = load_batch(nb, start, is64);

    int i = start;
    for (; i + 4 <= end; i += 4) {
        // ---- front-batched independent loads (MLP 8 per warp per iter) ----
        const int b0 = load_batch(nb, i + 0, is64);
        const int b1 = load_batch(nb, i + 1, is64);
        const int b2 = load_batch(nb, i + 2, is64);
        const int b3 = load_batch(nb, i + 3, is64);

        const float4 nv0 = __ldcs(&n4[(i + 0) * D4 + lane]);
        const float4 nv1 = __ldcs(&n4[(i + 1) * D4 + lane]);
        const float4 nv2 = __ldcs(&n4[(i + 2) * D4 + lane]);
        const float4 nv3 = __ldcs(&n4[(i + 3) * D4 + lane]);

        const float4 gv0 = __ldg(&g4[b0 * D4 + lane]);
        const float4 gv1 = __ldg(&g4[b1 * D4 + lane]);
        const float4 gv2 = __ldg(&g4[b2 * D4 + lane]);
        const float4 gv3 = __ldg(&g4[b3 * D4 + lane]);

        const float d0 = dot4(nv0, gv0);
        const float d1 = dot4(nv1, gv1);
        const float d2 = dot4(nv2, gv2);
        const float d3 = dot4(nv3, gv3);

        float c0, c1, c2, c3;
        reduce4_sigmoid(d0, d1, d2, d3, c0, c1, c2, c3, lane);

        // ---- ordered segment accumulation (rare flush branches) ----
        if (b0 != cur_b) { flush_seg(out, cur_b, lane, acc); acc = make_float4(0,0,0,0); cur_b = b0; }
        acc_add(acc, c0, nv0);
        if (b1 != cur_b) { flush_seg(out, cur_b, lane, acc); acc = make_float4(0,0,0,0); cur_b = b1; }
        acc_add(acc, c1, nv1);
        if (b2 != cur_b) { flush_seg(out, cur_b, lane, acc); acc = make_float4(0,0,0,0); cur_b = b2; }
        acc_add(acc, c2, nv2);
        if (b3 != cur_b) { flush_seg(out, cur_b, lane, acc); acc = make_float4(0,0,0,0); cur_b = b3; }
        acc_add(acc, c3, nv3);
    }

    // tail (only possible in the very last warp)
    for (; i < end; ++i) {
        const int b = load_batch(nb, i, is64);
        const float4 nv = __ldcs(&n4[i * D4 + lane]);
        const float4 gv = __ldg(&g4[b * D4 + lane]);
        float d = dot4(nv, gv);
        #pragma unroll
        for (int o = 16; o > 0; o >>= 1)
            d += __shfl_xor_sync(0xffffffffu, d, o);
        const float coef = sigmoidf_(d);
        if (b != cur_b) { flush_seg(out, cur_b, lane, acc); acc = make_float4(0,0,0,0); cur_b = b; }
        acc_add(acc, coef, nv);
    }

    flush_seg(out, cur_b, lane, acc);
}

extern "C" void kernel_launch(void* const* d_in, const int* in_sizes, int n_in,
                              void* d_out, int out_size) {
    const float4* n4 = (const float4*)d_in[0];   // n_embedding [N,128] f32
    const float4* g4 = (const float4*)d_in[1];   // g_embedding [G,128] f32
    const void*   nb = d_in[2];                  // n_batch [N] int32 or int64
    float* out = (float*)d_out;                  // [G,128] f32

    const int N = in_sizes[0] / D;

    init_kernel<<<(out_size + 255) / 256, 256>>>(out, out_size, (const int*)nb, N);

    const int total_warps  = (N + NODES_PER_WARP - 1) / NODES_PER_WARP;
    const int total_blocks = (total_warps + WARPS_PER_BLOCK - 1) / WARPS_PER_BLOCK;
    n2g_attention_kernel<<<total_blocks, THREADS>>>(n4, g4, nb, out, N);
}